// round 3
// baseline (speedup 1.0000x reference)
#include <cuda_runtime.h>
#include <math.h>
#include <stdint.h>

#define NQ      1024
#define NTRAIN  100000
#define DIM     64
#define KNN     16
#define NCLS    10

#define QB      8        // queries per CTA (one warp per query for selection)
#define TT      512      // train rows per tile
#define KC      8        // k-slice per smem stage
#define TPAD    520      // padded row stride (words) for conflict-free transposed tile
#define NSPLIT  8        // split of N across CTAs in y
#define CHUNK   (TT*25)  // 12800 rows per split
#define THREADS_A 256

// ---------------- static scratch (no allocation allowed) ----------------
__device__ float g_t2[NTRAIN];
__device__ float g_q2[NQ];
__device__ float g_pd[NQ * NSPLIT * KNN];
__device__ int   g_pi[NQ * NSPLIT * KNN];

// ---------------- helpers ----------------
__device__ __forceinline__ float finf() { return __int_as_float(0x7f800000); }

__device__ __forceinline__ void fma2(unsigned long long &a, unsigned long long b, unsigned long long c) {
    asm("fma.rn.f32x2 %0, %1, %2, %0;" : "+l"(a) : "l"(b), "l"(c));
}
__device__ __forceinline__ unsigned long long pack2(float v) {
    unsigned long long r;
    asm("mov.b64 %0, {%1, %1};" : "=l"(r) : "f"(v));
    return r;
}
__device__ __forceinline__ float2 unpack2(unsigned long long a) {
    float2 r;
    asm("mov.b64 {%0, %1}, %2;" : "=f"(r.x), "=f"(r.y) : "l"(a));
    return r;
}

// ---------------- kernel 0: row sum-of-squares for train and x ----------------
__global__ void __launch_bounds__(256) sumsq_kernel(const float* __restrict__ train,
                                                    const float* __restrict__ x) {
    int i = blockIdx.x * 256 + threadIdx.x;
    const float* row;
    float* dst;
    if (i < NTRAIN)            { row = train + (size_t)i * DIM;            dst = &g_t2[i]; }
    else if (i < NTRAIN + NQ)  { row = x + (size_t)(i - NTRAIN) * DIM;     dst = &g_q2[i - NTRAIN]; }
    else return;
    const float4* r4 = (const float4*)row;
    float s = 0.f;
    #pragma unroll
    for (int j = 0; j < DIM/4; ++j) {
        float4 v = r4[j];
        s += v.x*v.x + v.y*v.y + v.z*v.z + v.w*v.w;
    }
    *dst = s;
}

// ---------------- kernel A: tiled distances + per-split top-16 ----------------
__global__ void __launch_bounds__(THREADS_A) knn_partial_kernel(const float* __restrict__ x,
                                                                const float* __restrict__ train) {
    __shared__ float tT[KC * TPAD];     // transposed tile [k][row]
    __shared__ float d2s[QB * TT];      // per-tile distance block
    __shared__ float qTs[DIM * QB];     // transposed queries [k][q]
    __shared__ float q2s[QB];

    const int tid   = threadIdx.x;
    const int lane  = tid & 31;
    const int w     = tid >> 5;          // warp id == query slot for selection
    const int qblk  = blockIdx.x;        // 0..127
    const int split = blockIdx.y;        // 0..NSPLIT-1
    const int qbase = qblk * QB;

    // ---- stage queries (k-major) + q2 ----
    for (int i = tid; i < QB * DIM; i += THREADS_A) {
        int q = i >> 6, k = i & 63;
        qTs[k * QB + q] = x[(size_t)(qbase + q) * DIM + k];
    }
    if (tid < QB) q2s[tid] = g_q2[qbase + tid];
    __syncthreads();

    // ---- per-lane running top-16 (sorted ascending) for query w ----
    float td[KNN]; int ti[KNN];
    #pragma unroll
    for (int j = 0; j < KNN; ++j) { td[j] = finf(); ti[j] = 0x7fffffff; }

    const int qg = tid >> 7;     // 0..1 : 4-query group
    const int rg = tid & 127;    // 0..127: 4-row group

    const int rowbase0 = split * CHUNK;
    int ntiles = (NTRAIN - rowbase0 + TT - 1) / TT;
    if (ntiles > CHUNK / TT) ntiles = CHUNK / TT;

    for (int t = 0; t < ntiles; ++t) {
        const int rowbase = rowbase0 + t * TT;

        unsigned long long acc[4][2];
        #pragma unroll
        for (int a = 0; a < 4; ++a) { acc[a][0] = 0ULL; acc[a][1] = 0ULL; }

        #pragma unroll 1
        for (int ks = 0; ks < DIM / KC; ++ks) {
            __syncthreads();   // previous compute done with tT
            // load KC-slice of TT rows, transposed; 2 rows per thread, coalesced
            {
                const int r0 = tid * 2;
                #pragma unroll
                for (int rr = 0; rr < 2; ++rr) {
                    const int r = r0 + rr;
                    const long g = (long)rowbase + r;
                    float4 v0, v1;
                    if (g < NTRAIN) {
                        const float4* src = (const float4*)(train + (size_t)g * DIM + ks * KC);
                        v0 = src[0]; v1 = src[1];
                    } else {
                        v0 = make_float4(0.f,0.f,0.f,0.f); v1 = v0;
                    }
                    float* col = tT + r;
                    col[0*TPAD] = v0.x; col[1*TPAD] = v0.y; col[2*TPAD] = v0.z; col[3*TPAD] = v0.w;
                    col[4*TPAD] = v1.x; col[5*TPAD] = v1.y; col[6*TPAD] = v1.z; col[7*TPAD] = v1.w;
                }
            }
            __syncthreads();
            // 4q x 4r micro-tile, packed f32x2 over row pairs
            #pragma unroll
            for (int k = 0; k < KC; ++k) {
                const float4 qf = *(const float4*)(qTs + (ks * KC + k) * QB + qg * 4);
                const ulonglong2 tt = *(const ulonglong2*)(tT + k * TPAD + rg * 4);
                unsigned long long qq;
                qq = pack2(qf.x); fma2(acc[0][0], tt.x, qq); fma2(acc[0][1], tt.y, qq);
                qq = pack2(qf.y); fma2(acc[1][0], tt.x, qq); fma2(acc[1][1], tt.y, qq);
                qq = pack2(qf.z); fma2(acc[2][0], tt.x, qq); fma2(acc[2][1], tt.y, qq);
                qq = pack2(qf.w); fma2(acc[3][0], tt.x, qq); fma2(acc[3][1], tt.y, qq);
            }
        }

        // ---- epilogue: d2 = q2 + t2 - 2*dot (OOB rows get t2 = +inf) ----
        float t2v[4];
        #pragma unroll
        for (int m = 0; m < 4; ++m) {
            long g = (long)rowbase + rg * 4 + m;
            t2v[m] = (g < NTRAIN) ? g_t2[g] : finf();
        }
        #pragma unroll
        for (int qi = 0; qi < 4; ++qi) {
            const float q2v = q2s[qg * 4 + qi];
            float2 a0 = unpack2(acc[qi][0]);
            float2 a1 = unpack2(acc[qi][1]);
            float4 o;
            o.x = fmaf(-2.f, a0.x, q2v + t2v[0]);
            o.y = fmaf(-2.f, a0.y, q2v + t2v[1]);
            o.z = fmaf(-2.f, a1.x, q2v + t2v[2]);
            o.w = fmaf(-2.f, a1.y, q2v + t2v[3]);
            *(float4*)(d2s + (qg * 4 + qi) * TT + rg * 4) = o;
        }
        __syncthreads();

        // ---- selection: warp w scans query w's 512 distances ----
        #pragma unroll
        for (int j = 0; j < TT / 32; ++j) {
            const int r = lane + 32 * j;
            const float d = d2s[w * TT + r];
            if (d < td[KNN - 1]) {
                float cd = d; int ci = rowbase + r;
                #pragma unroll
                for (int s = 0; s < KNN; ++s) {
                    if (cd < td[s]) {
                        float tf = td[s]; td[s] = cd; cd = tf;
                        int   tg = ti[s]; ti[s] = ci; ci = tg;
                    }
                }
            }
        }
        // next tile's first __syncthreads guards d2s/tT reuse
    }

    // ---- warp merge: 32 lanes x 16 -> split top-16 ----
    __syncthreads();
    float* md = tT;            // reuse: 8 warps * 512 floats <= 8*520
    int*   mi = (int*)d2s;     // reuse: 8 warps * 512 ints
    #pragma unroll
    for (int j = 0; j < KNN; ++j) {
        md[w * TT + lane * KNN + j] = td[j];
        mi[w * TT + lane * KNN + j] = ti[j];
    }
    __syncwarp();

    float* outd = g_pd + ((size_t)(qbase + w) * NSPLIT + split) * KNN;
    int*   outi = g_pi + ((size_t)(qbase + w) * NSPLIT + split) * KNN;
    int head = 0;
    for (int j = 0; j < KNN; ++j) {
        float v  = (head < KNN) ? md[w * TT + lane * KNN + head] : finf();
        int   gi = (head < KNN) ? mi[w * TT + lane * KNN + head] : 0x7fffffff;
        float bv = v; int bi = gi; int bl = lane;
        #pragma unroll
        for (int off = 16; off; off >>= 1) {
            float ov = __shfl_down_sync(0xffffffffu, bv, off);
            int   oi = __shfl_down_sync(0xffffffffu, bi, off);
            int   ol = __shfl_down_sync(0xffffffffu, bl, off);
            if (ov < bv || (ov == bv && oi < bi)) { bv = ov; bi = oi; bl = ol; }
        }
        bv = __shfl_sync(0xffffffffu, bv, 0);
        bi = __shfl_sync(0xffffffffu, bi, 0);
        bl = __shfl_sync(0xffffffffu, bl, 0);
        if (lane == bl) head++;
        if (lane == 0) { outd[j] = bv; outi[j] = bi; }
    }
}

// ---------------- kernel B: merge splits, weights, proba, argmax ----------------
// labels is int32 (JAX default x64-disabled demotes jnp.int64 -> int32).
__global__ void __launch_bounds__(256) knn_finalize_kernel(const int* __restrict__ labels,
                                                           float* __restrict__ outF,
                                                           int* __restrict__ outI,
                                                           int mode) {
    const int lane = threadIdx.x & 31;
    const int w    = threadIdx.x >> 5;
    const int q    = blockIdx.x * 8 + w;

    // 128 candidates per query: 4 per lane
    float bd[4]; int bidx[4];
    #pragma unroll
    for (int m = 0; m < 4; ++m) {
        int e = q * (NSPLIT * KNN) + lane * 4 + m;
        bd[m] = g_pd[e]; bidx[m] = g_pi[e];
    }
    unsigned tk = 0;
    float sd[KNN]; int si[KNN];
    for (int j = 0; j < KNN; ++j) {
        float lv = finf(); int li = 0x7fffffff; int ls = 0;
        #pragma unroll
        for (int m = 0; m < 4; ++m) {
            bool avail = !((tk >> m) & 1u);
            if (avail && (bd[m] < lv || (bd[m] == lv && bidx[m] < li))) { lv = bd[m]; li = bidx[m]; ls = m; }
        }
        float bv = lv; int bi = li; int bl = lane;
        #pragma unroll
        for (int off = 16; off; off >>= 1) {
            float ov = __shfl_down_sync(0xffffffffu, bv, off);
            int   oi = __shfl_down_sync(0xffffffffu, bi, off);
            int   ol = __shfl_down_sync(0xffffffffu, bl, off);
            if (ov < bv || (ov == bv && oi < bi)) { bv = ov; bi = oi; bl = ol; }
        }
        bv = __shfl_sync(0xffffffffu, bv, 0);
        bi = __shfl_sync(0xffffffffu, bi, 0);
        bl = __shfl_sync(0xffffffffu, bl, 0);
        if (lane == bl) tk |= (1u << ls);
        sd[j] = bv; si[j] = bi;
    }

    if (lane == 0) {
        float dist[KNN]; int lab[KNN]; bool anyz = false;
        #pragma unroll
        for (int j = 0; j < KNN; ++j) {
            float d2 = sd[j]; d2 = d2 > 0.f ? d2 : 0.f;
            float d = sqrtf(d2);
            dist[j] = d;
            if (d == 0.f) anyz = true;
            // guard: clamp index defensively (should always be valid)
            int idx = si[j];
            idx = (idx >= 0 && idx < NTRAIN) ? idx : 0;
            lab[j] = labels[idx];
        }
        float p[NCLS];
        #pragma unroll
        for (int c = 0; c < NCLS; ++c) p[c] = 0.f;
        #pragma unroll
        for (int j = 0; j < KNN; ++j) {
            float wj = anyz ? (dist[j] == 0.f ? 1.f : 0.f) : (1.f / dist[j]);
            int lc = lab[j];
            lc = (lc >= 0 && lc < NCLS) ? lc : 0;
            p[lc] += wj;
        }
        float s = 0.f;
        #pragma unroll
        for (int c = 0; c < NCLS; ++c) s += p[c];
        if (s == 0.f) s = 1.f;
        int am = 0; float bvp = -1.f;
        #pragma unroll
        for (int c = 0; c < NCLS; ++c) {
            p[c] = p[c] / s;
            if (p[c] > bvp) { bvp = p[c]; am = c; }
        }
        if (mode == 0) {
            // flattened tuple: argmax (as float) first, then proba [NQ x NCLS]
            outF[q] = (float)am;
            #pragma unroll
            for (int c = 0; c < NCLS; ++c) outF[NQ + q * NCLS + c] = p[c];
        } else if (mode == 1) {
            #pragma unroll
            for (int c = 0; c < NCLS; ++c) outF[q * NCLS + c] = p[c];
        } else {
            outI[q] = am;   // int32 argmax only
        }
    }
}

// ---------------- launch ----------------
extern "C" void kernel_launch(void* const* d_in, const int* in_sizes, int n_in,
                              void* d_out, int out_size) {
    const float* x      = (const float*)d_in[0];
    const float* train  = (const float*)d_in[1];
    const int*   labels = (const int*)d_in[2];   // int32 (see kernel B note)
    (void)in_sizes; (void)n_in;

    sumsq_kernel<<<(NTRAIN + NQ + 255) / 256, 256>>>(train, x);

    dim3 gA(NQ / QB, NSPLIT);
    knn_partial_kernel<<<gA, THREADS_A>>>(x, train);

    int mode;
    if (out_size == NQ * (NCLS + 1)) mode = 0;
    else if (out_size == NQ * NCLS)  mode = 1;
    else if (out_size == NQ)         mode = 2;
    else                             mode = 0;

    knn_finalize_kernel<<<NQ / 8, 256>>>(labels, (float*)d_out, (int*)d_out, mode);
}